// round 2
// baseline (speedup 1.0000x reference)
#include <cuda_runtime.h>
#include <cuda_bf16.h>
#include <cstdint>

// Problem constants (fixed by the dataset)
#define D_MODEL   256
#define N_EXP     16
#define MAX_B     65536
#define BLK_TOK   256     // reference mask-block size (== D_MODEL)

// Main GEMM tiling
#define BM  128
#define BN  256
#define BK  32
#define NT  512           // threads in main kernel
#define NSLAB (N_EXP * (D_MODEL / BK))   // 16 * 8 = 128 W slabs

// Scratch (allocation-free rule: __device__ globals)
__device__ float    g_coef[MAX_B * N_EXP];          // softmax probs per token
__device__ unsigned g_maskbits[MAX_B / BLK_TOK];    // 16-bit active-expert mask per 256-token block

// ---------------------------------------------------------------------------
// Kernel 0: zero the per-block expert masks (must precede gate kernel)
// ---------------------------------------------------------------------------
__global__ void zero_mask_kernel() {
    g_maskbits[threadIdx.x] = 0u;
}

// ---------------------------------------------------------------------------
// Kernel 1: gating. One warp per token.
//   logits = x @ gate_w^T + gate_b ; probs = softmax ; top-1 -> block bitmask
// ---------------------------------------------------------------------------
__global__ void gate_kernel(const float* __restrict__ x,
                            const float* __restrict__ gw,
                            const float* __restrict__ gb,
                            int B) {
    __shared__ float s_gw[N_EXP * D_MODEL];
    __shared__ float s_gb[N_EXP];
    int tid = threadIdx.x;
    for (int i = tid; i < N_EXP * D_MODEL; i += 256) s_gw[i] = gw[i];
    if (tid < N_EXP) s_gb[tid] = gb[tid];
    __syncthreads();

    int warp = tid >> 5, lane = tid & 31;
    int token = blockIdx.x * 8 + warp;
    if (token >= B) return;

    const float* xr = x + (size_t)token * D_MODEL;
    float xv[8];
#pragma unroll
    for (int i = 0; i < 8; i++) xv[i] = xr[lane + 32 * i];

    float logits[N_EXP];
#pragma unroll
    for (int e = 0; e < N_EXP; e++) {
        float p = 0.f;
#pragma unroll
        for (int i = 0; i < 8; i++) p += xv[i] * s_gw[e * D_MODEL + lane + 32 * i];
#pragma unroll
        for (int off = 16; off > 0; off >>= 1) p += __shfl_xor_sync(0xffffffffu, p, off);
        logits[e] = p + s_gb[e];
    }

    // softmax over 16 experts (replicated in every lane)
    float mx = logits[0]; int amax = 0;
#pragma unroll
    for (int e = 1; e < N_EXP; e++) if (logits[e] > mx) { mx = logits[e]; amax = e; }
    float sum = 0.f;
#pragma unroll
    for (int e = 0; e < N_EXP; e++) { logits[e] = expf(logits[e] - mx); sum += logits[e]; }
    float inv = 1.f / sum;

    if (lane < N_EXP) g_coef[(size_t)token * N_EXP + lane] = logits[lane] * inv;
    if (lane == 0)    atomicOr(&g_maskbits[token >> 8], 1u << amax);
}

// ---------------------------------------------------------------------------
// Kernel 2: fused masked-MoE GEMM.
//   out[128x256 tile] = sum_e (probs[:,e]*maskbit) * (Xtile @ W_e)
//   Xtile (128x256 f32) resident in SMEM; W streamed in 32x256 slabs
//   via double-buffered cp.async. Coefficient folded into A operand.
// ---------------------------------------------------------------------------
__device__ __forceinline__ unsigned smem_u32(const void* p) {
    return (unsigned)__cvta_generic_to_shared(p);
}
__device__ __forceinline__ void cp_async16(void* smem_dst, const void* gmem_src) {
    asm volatile("cp.async.cg.shared.global [%0], [%1], 16;\n"
                 :: "r"(smem_u32(smem_dst)), "l"(gmem_src));
}
__device__ __forceinline__ void cp_commit() {
    asm volatile("cp.async.commit_group;\n");
}
__device__ __forceinline__ void cp_wait1() {
    asm volatile("cp.async.wait_group 1;\n");
}
__device__ __forceinline__ void cp_wait0() {
    asm volatile("cp.async.wait_group 0;\n");
}
__device__ __forceinline__ void ffma4(float4& acc, float a, const float4& b) {
    acc.x = fmaf(a, b.x, acc.x);
    acc.y = fmaf(a, b.y, acc.y);
    acc.z = fmaf(a, b.z, acc.z);
    acc.w = fmaf(a, b.w, acc.w);
}

__global__ __launch_bounds__(NT, 1)
void moe_kernel(const float* __restrict__ x,
                const float* __restrict__ w,
                float* __restrict__ out) {
    extern __shared__ float sm[];
    float* s_x = sm;                        // BM * 256
    float* s_w = s_x + BM * D_MODEL;        // 2 * BK * BN
    float* s_c = s_w + 2 * BK * BN;         // BM * 16

    const int tid = threadIdx.x;
    const int tn  = tid & 15;               // column group 0..15
    const int tg  = tid >> 4;               // row group 0..31 (4 rows each)
    const size_t t0 = (size_t)blockIdx.x * BM;

    // ---- load X tile (float4, fully coalesced) ----
    {
        const float4* xg  = (const float4*)(x + t0 * D_MODEL);
        float4*       sx4 = (float4*)s_x;
#pragma unroll
        for (int i = 0; i < (BM * D_MODEL / 4) / NT; i++)   // 16 iters
            sx4[tid + NT * i] = xg[tid + NT * i];
    }
    // ---- load combined coefficients = probs * mask_block bit ----
    {
        unsigned mb = g_maskbits[t0 >> 8];
#pragma unroll
        for (int i = 0; i < (BM * N_EXP) / NT; i++) {       // 4 iters
            int idx = tid + NT * i;
            int e = idx & 15;
            float c = g_coef[t0 * N_EXP + idx];
            s_c[idx] = ((mb >> e) & 1u) ? c : 0.f;
        }
    }

    // ---- issue W slab 0 ----
    auto issue = [&](int s) {
        const int e  = s >> 3;
        const int ks = s & 7;
        float* dst = s_w + (size_t)(s & 1) * BK * BN;
        const float* src = w + (size_t)(ks * BK) * (N_EXP * D_MODEL) + e * D_MODEL;
#pragma unroll
        for (int i = 0; i < (BK * BN / 4) / NT; i++) {      // 4 iters
            int idx4 = tid + NT * i;
            int r  = idx4 >> 6;                              // 64 float4 per row
            int c4 = idx4 & 63;
            cp_async16(dst + idx4 * 4, src + (size_t)r * (N_EXP * D_MODEL) + c4 * 4);
        }
        cp_commit();
    };
    issue(0);

    float4 acc[4][4];
#pragma unroll
    for (int i = 0; i < 4; i++)
#pragma unroll
        for (int j = 0; j < 4; j++) acc[i][j] = make_float4(0.f, 0.f, 0.f, 0.f);

    for (int s = 0; s < NSLAB; s++) {
        if (s + 1 < NSLAB) { issue(s + 1); cp_wait1(); }
        else               { cp_wait0(); }
        __syncthreads();

        const int e  = s >> 3;
        const int ka = (s & 7) * BK;                         // absolute k base
        const float* wbuf = s_w + (size_t)(s & 1) * BK * BN;

        float cc[4];
#pragma unroll
        for (int i = 0; i < 4; i++) cc[i] = s_c[(tg * 4 + i) * N_EXP + e];

#pragma unroll 8
        for (int kk = 0; kk < BK; kk++) {
            float a[4];
#pragma unroll
            for (int i = 0; i < 4; i++)
                a[i] = s_x[(tg * 4 + i) * D_MODEL + ka + kk] * cc[i];
            float4 b[4];
#pragma unroll
            for (int j = 0; j < 4; j++)
                b[j] = *(const float4*)(wbuf + kk * BN + tn * 4 + 64 * j);
#pragma unroll
            for (int i = 0; i < 4; i++)
#pragma unroll
                for (int j = 0; j < 4; j++)
                    ffma4(acc[i][j], a[i], b[j]);
        }
        __syncthreads();
    }

    // ---- epilogue: coalesced float4 stores ----
#pragma unroll
    for (int i = 0; i < 4; i++) {
        float* orow = out + (t0 + tg * 4 + i) * D_MODEL;
#pragma unroll
        for (int j = 0; j < 4; j++)
            *(float4*)(orow + tn * 4 + 64 * j) = acc[i][j];
    }
}

// ---------------------------------------------------------------------------
// Launch
// ---------------------------------------------------------------------------
extern "C" void kernel_launch(void* const* d_in, const int* in_sizes, int n_in,
                              void* d_out, int out_size) {
    const float* x  = (const float*)d_in[0];
    const float* w  = (const float*)d_in[1];
    const float* gw = (const float*)d_in[2];
    const float* gb = (const float*)d_in[3];
    float* out = (float*)d_out;

    int B = in_sizes[0] / D_MODEL;

    zero_mask_kernel<<<1, MAX_B / BLK_TOK>>>();
    gate_kernel<<<B / 8, 256>>>(x, gw, gb, B);

    size_t smem = (size_t)(BM * D_MODEL + 2 * BK * BN + BM * N_EXP) * sizeof(float);
    cudaFuncSetAttribute(moe_kernel, cudaFuncAttributeMaxDynamicSharedMemorySize, (int)smem);
    moe_kernel<<<B / BM, NT, smem>>>(x, w, out);
}

// round 5
// speedup vs baseline: 3.6775x; 3.6775x over previous
#include <cuda_runtime.h>
#include <cstdint>

#define D_MODEL   256
#define N_EXP     16
#define MAX_B     65536

// ---------------------------------------------------------------------------
// Device-global scratch (allocation-free rule)
// ---------------------------------------------------------------------------
__device__ float    g_A [(size_t)MAX_B * D_MODEL];              // tf32(rna) x, natural layout
__device__ float    g_Bt[(size_t)D_MODEL * N_EXP * D_MODEL];    // tf32(rna) w, natural layout
__device__ float    g_coef[(size_t)MAX_B * N_EXP];
__device__ unsigned g_maskbits[MAX_B / 256];

// ---------------------------------------------------------------------------
// Helpers
// ---------------------------------------------------------------------------
__device__ __forceinline__ uint32_t smem_u32(const void* p) {
    return (uint32_t)__cvta_generic_to_shared(p);
}
__device__ __forceinline__ float f2tf32(float f) {
    uint32_t r;
    asm("cvt.rna.tf32.f32 %0, %1;" : "=r"(r) : "f"(f));
    return __uint_as_float(r);
}
__device__ __forceinline__ void cp_async16(void* smem_dst, const void* gmem_src) {
    asm volatile("cp.async.cg.shared.global [%0], [%1], 16;\n"
                 :: "r"(smem_u32(smem_dst)), "l"(gmem_src));
}
__device__ __forceinline__ void cp_commit() {
    asm volatile("cp.async.commit_group;\n");
}
__device__ __forceinline__ void cp_wait1() {
    asm volatile("cp.async.wait_group 1;\n");
}
__device__ __forceinline__ void cp_wait0() {
    asm volatile("cp.async.wait_group 0;\n");
}
// Legacy tensor-core MMA (sm_80+, valid on base sm_100 target):
// D[16x8] += A[16x8] * B[8x8], tf32 inputs (b32 regs), f32 accum.
__device__ __forceinline__ void mma_tf32(float& c0, float& c1, float& c2, float& c3,
                                         uint32_t a0, uint32_t a1, uint32_t a2, uint32_t a3,
                                         uint32_t b0, uint32_t b1) {
    asm volatile(
        "mma.sync.aligned.m16n8k8.row.col.f32.tf32.tf32.f32 "
        "{%0,%1,%2,%3}, {%4,%5,%6,%7}, {%8,%9}, {%0,%1,%2,%3};\n"
        : "+f"(c0), "+f"(c1), "+f"(c2), "+f"(c3)
        : "r"(a0), "r"(a1), "r"(a2), "r"(a3), "r"(b0), "r"(b1));
}

// ---------------------------------------------------------------------------
// Kernel: zero block masks
// ---------------------------------------------------------------------------
__global__ void zero_mask_kernel(int n) {
    int i = blockIdx.x * 256 + threadIdx.x;
    if (i < n) g_maskbits[i] = 0u;
}

// ---------------------------------------------------------------------------
// Kernel: gating (one warp per token) — proven in Rounds 1-2
// ---------------------------------------------------------------------------
__global__ void gate_kernel(const float* __restrict__ x,
                            const float* __restrict__ gw,
                            const float* __restrict__ gb,
                            int B) {
    __shared__ float s_gw[N_EXP * D_MODEL];
    __shared__ float s_gb[N_EXP];
    int tid = threadIdx.x;
    for (int i = tid; i < N_EXP * D_MODEL; i += 256) s_gw[i] = gw[i];
    if (tid < N_EXP) s_gb[tid] = gb[tid];
    __syncthreads();

    int warp = tid >> 5, lane = tid & 31;
    int token = blockIdx.x * 8 + warp;
    if (token >= B) return;

    const float* xr = x + (size_t)token * D_MODEL;
    float xv[8];
#pragma unroll
    for (int i = 0; i < 8; i++) xv[i] = xr[lane + 32 * i];

    float logits[N_EXP];
#pragma unroll
    for (int e = 0; e < N_EXP; e++) {
        float p = 0.f;
#pragma unroll
        for (int i = 0; i < 8; i++) p += xv[i] * s_gw[e * D_MODEL + lane + 32 * i];
#pragma unroll
        for (int off = 16; off > 0; off >>= 1) p += __shfl_xor_sync(0xffffffffu, p, off);
        logits[e] = p + s_gb[e];
    }
    float mx = logits[0]; int amax = 0;
#pragma unroll
    for (int e = 1; e < N_EXP; e++) if (logits[e] > mx) { mx = logits[e]; amax = e; }
    float sum = 0.f;
#pragma unroll
    for (int e = 0; e < N_EXP; e++) { logits[e] = expf(logits[e] - mx); sum += logits[e]; }
    float inv = 1.f / sum;
    if (lane < N_EXP) g_coef[(size_t)token * N_EXP + lane] = logits[lane] * inv;
    if (lane == 0)    atomicOr(&g_maskbits[token >> 8], 1u << amax);
}

// ---------------------------------------------------------------------------
// Kernels: elementwise rna-round to tf32 (removes HW-truncation bias)
// ---------------------------------------------------------------------------
__global__ void prep_A_kernel(const float* __restrict__ x, int n4) {
    int i = blockIdx.x * 256 + threadIdx.x;
    if (i >= n4) return;
    float4 v = ((const float4*)x)[i];
    v.x = f2tf32(v.x); v.y = f2tf32(v.y); v.z = f2tf32(v.z); v.w = f2tf32(v.w);
    ((float4*)g_A)[i] = v;
}
__global__ void prep_B_kernel(const float* __restrict__ w, int n4) {
    int i = blockIdx.x * 256 + threadIdx.x;
    if (i >= n4) return;
    float4 v = ((const float4*)w)[i];
    v.x = f2tf32(v.x); v.y = f2tf32(v.y); v.z = f2tf32(v.z); v.w = f2tf32(v.w);
    ((float4*)g_Bt)[i] = v;
}

// ---------------------------------------------------------------------------
// Main kernel: legacy-HMMA tf32 MoE GEMM.
//   CTA = 128 tokens x 128 out-cols, 256 threads (8 warps, warp tile 64x32).
//   A tile (128x256 tf32) SMEM-resident, reused by all 16 experts.
//   B streamed per (expert e, k-slab kc) = 32x128, 3-buffer cp.async ring.
//   Per expert: cfrag += A@B_e; at expert end: out += coef[row,e]*cfrag.
// ---------------------------------------------------------------------------
#define ASTRIDE 260          // floats/row, %32==4  -> conflict-free a-frags
#define BSTRIDE 136          // floats/row, %32==8  -> conflict-free b-frags
#define CSTRIDE 17
#define SM_A_OFF 0
#define SM_B_OFF (128 * ASTRIDE)                  // 33280
#define SM_C_OFF (SM_B_OFF + 3 * 32 * BSTRIDE)    // 46336
#define SMEM_FLOATS (SM_C_OFF + 128 * CSTRIDE)    // 48512
#define SMEM_BYTES  (SMEM_FLOATS * 4)             // 194048

__global__ void __launch_bounds__(256, 1)
moe_mma_kernel(float* __restrict__ out, int B) {
    extern __shared__ float sm[];
    float* s_a = sm + SM_A_OFF;
    float* s_c = sm + SM_C_OFF;

    const int tid  = threadIdx.x;
    const int wid  = tid >> 5;
    const int lane = tid & 31;
    const int gid  = lane >> 2;          // 0..7
    const int tig  = lane & 3;           // 0..3
    const int warp_m = wid & 1;          // 0..1 (64 rows each)
    const int warp_n = wid >> 1;         // 0..3 (32 cols each)

    const int mblk  = blockIdx.x >> 1;
    const int nhalf = blockIdx.x & 1;
    const size_t t0 = (size_t)mblk * 128;

    // ---- coefficients (masked) into SMEM ----
    {
        unsigned mb = g_maskbits[(unsigned)(t0 >> 8)];
#pragma unroll
        for (int it = 0; it < 8; it++) {
            int idx = it * 256 + tid;        // 128*16 = 2048
            int r = idx >> 4, e = idx & 15;
            float c = g_coef[(t0 + r) * N_EXP + e];
            s_c[r * CSTRIDE + e] = ((mb >> e) & 1u) ? c : 0.f;
        }
    }

    // ---- A tile: 128 x 256 floats via cp.async ----
    {
        const float* asrc = g_A + t0 * D_MODEL;
#pragma unroll
        for (int it = 0; it < 32; it++) {
            int idx = it * 256 + tid;        // float4 index, 8192 total
            int r = idx >> 6, c4 = idx & 63;
            cp_async16(s_a + r * ASTRIDE + c4 * 4, asrc + r * D_MODEL + c4 * 4);
        }
    }
    // ---- slab issue helper: slab i = (e = i>>3, kc = i&7), 32x128 ----
    auto issue_slab = [&](int i) {
        int e = i >> 3, kc = i & 7;
        float* dst = sm + SM_B_OFF + (i % 3) * (32 * BSTRIDE);
        const float* src = g_Bt + (size_t)(kc * 32) * (N_EXP * D_MODEL)
                         + e * D_MODEL + nhalf * 128;
#pragma unroll
        for (int it = 0; it < 4; it++) {
            int idx = it * 256 + tid;        // float4 index, 1024 total
            int kr = idx >> 5, c4 = idx & 31;
            cp_async16(dst + kr * BSTRIDE + c4 * 4,
                       src + (size_t)kr * (N_EXP * D_MODEL) + c4 * 4);
        }
        cp_commit();
    };
    issue_slab(0);   // group: {A + slab0}

    float o[4][4][4];
#pragma unroll
    for (int mt = 0; mt < 4; mt++)
#pragma unroll
        for (int nt = 0; nt < 4; nt++)
#pragma unroll
            for (int j = 0; j < 4; j++) o[mt][nt][j] = 0.f;

    float cf[4][4][4];

    const uint32_t* s_au = (const uint32_t*)s_a;

#pragma unroll 1
    for (int i = 0; i < 128; i++) {
        const int kc = i & 7;
        if (i + 1 < 128) { issue_slab(i + 1); cp_wait1(); }
        else             { cp_wait0(); }
        __syncthreads();

        if (kc == 0) {
#pragma unroll
            for (int mt = 0; mt < 4; mt++)
#pragma unroll
                for (int nt = 0; nt < 4; nt++)
#pragma unroll
                    for (int j = 0; j < 4; j++) cf[mt][nt][j] = 0.f;
        }

        const uint32_t* bb = (const uint32_t*)(sm + SM_B_OFF + (i % 3) * (32 * BSTRIDE));

#pragma unroll
        for (int k8 = 0; k8 < 4; k8++) {
            const int kcol = kc * 32 + k8 * 8;
            uint32_t a[4][4];
#pragma unroll
            for (int mt = 0; mt < 4; mt++) {
                int row0 = warp_m * 64 + mt * 16 + gid;
                int base = row0 * ASTRIDE + kcol + tig;
                a[mt][0] = s_au[base];
                a[mt][1] = s_au[base + 8 * ASTRIDE];
                a[mt][2] = s_au[base + 4];
                a[mt][3] = s_au[base + 4 + 8 * ASTRIDE];
            }
            uint32_t b[4][2];
#pragma unroll
            for (int nt = 0; nt < 4; nt++) {
                int col = warp_n * 32 + nt * 8 + gid;
                b[nt][0] = bb[(k8 * 8 + tig) * BSTRIDE + col];
                b[nt][1] = bb[(k8 * 8 + tig + 4) * BSTRIDE + col];
            }
#pragma unroll
            for (int mt = 0; mt < 4; mt++)
#pragma unroll
                for (int nt = 0; nt < 4; nt++)
                    mma_tf32(cf[mt][nt][0], cf[mt][nt][1], cf[mt][nt][2], cf[mt][nt][3],
                             a[mt][0], a[mt][1], a[mt][2], a[mt][3],
                             b[nt][0], b[nt][1]);
        }

        if (kc == 7) {
            const int e = i >> 3;
#pragma unroll
            for (int mt = 0; mt < 4; mt++) {
                int r0 = warp_m * 64 + mt * 16 + gid;
                float c0 = s_c[r0 * CSTRIDE + e];
                float c1 = s_c[(r0 + 8) * CSTRIDE + e];
#pragma unroll
                for (int nt = 0; nt < 4; nt++) {
                    o[mt][nt][0] = fmaf(c0, cf[mt][nt][0], o[mt][nt][0]);
                    o[mt][nt][1] = fmaf(c0, cf[mt][nt][1], o[mt][nt][1]);
                    o[mt][nt][2] = fmaf(c1, cf[mt][nt][2], o[mt][nt][2]);
                    o[mt][nt][3] = fmaf(c1, cf[mt][nt][3], o[mt][nt][3]);
                }
            }
        }
    }

    // ---- epilogue: float2 stores (one 8B chunk per (row, ntile) pair) ----
#pragma unroll
    for (int mt = 0; mt < 4; mt++) {
        size_t r0 = t0 + warp_m * 64 + mt * 16 + gid;
#pragma unroll
        for (int nt = 0; nt < 4; nt++) {
            int col = nhalf * 128 + warp_n * 32 + nt * 8 + 2 * tig;
            *(float2*)(out + r0 * D_MODEL + col)       = make_float2(o[mt][nt][0], o[mt][nt][1]);
            *(float2*)(out + (r0 + 8) * D_MODEL + col) = make_float2(o[mt][nt][2], o[mt][nt][3]);
        }
    }
}

// ---------------------------------------------------------------------------
// Launch
// ---------------------------------------------------------------------------
extern "C" void kernel_launch(void* const* d_in, const int* in_sizes, int n_in,
                              void* d_out, int out_size) {
    const float* x  = (const float*)d_in[0];
    const float* w  = (const float*)d_in[1];
    const float* gw = (const float*)d_in[2];
    const float* gb = (const float*)d_in[3];
    float* out = (float*)d_out;

    int B = in_sizes[0] / D_MODEL;
    int nblk256 = B / 256;

    zero_mask_kernel<<<(nblk256 + 255) / 256, 256>>>(nblk256);
    gate_kernel<<<B / 8, 256>>>(x, gw, gb, B);

    int nA4 = (B * D_MODEL) / 4;
    int nB4 = (D_MODEL * N_EXP * D_MODEL) / 4;
    prep_A_kernel<<<(nA4 + 255) / 256, 256>>>(x, nA4);
    prep_B_kernel<<<(nB4 + 255) / 256, 256>>>(w, nB4);

    cudaFuncSetAttribute(moe_mma_kernel,
                         cudaFuncAttributeMaxDynamicSharedMemorySize, SMEM_BYTES);
    moe_mma_kernel<<<(B / 128) * 2, 256, SMEM_BYTES>>>(out, B);
}

// round 8
// speedup vs baseline: 5.1838x; 1.4096x over previous
#include <cuda_runtime.h>
#include <cuda_fp16.h>
#include <cstdint>

#define D_MODEL   256
#define N_EXP     16
#define MAX_B     65536

// ---------------------------------------------------------------------------
// Device-global scratch (allocation-free rule)
// ---------------------------------------------------------------------------
__device__ __half   g_Ah[(size_t)MAX_B * D_MODEL];              // fp16(rn) x, [b][k]
__device__ __half   g_Bh[(size_t)N_EXP * D_MODEL * D_MODEL];    // fp16(rn) w, TRANSPOSED [e][n][k]
__device__ float    g_coef[(size_t)MAX_B * N_EXP];
__device__ unsigned g_maskbits[MAX_B / 256];

// ---------------------------------------------------------------------------
// Helpers
// ---------------------------------------------------------------------------
__device__ __forceinline__ uint32_t smem_u32(const void* p) {
    return (uint32_t)__cvta_generic_to_shared(p);
}
__device__ __forceinline__ void cp_async16(void* smem_dst, const void* gmem_src) {
    asm volatile("cp.async.cg.shared.global [%0], [%1], 16;\n"
                 :: "r"(smem_u32(smem_dst)), "l"(gmem_src));
}
__device__ __forceinline__ void cp_commit() {
    asm volatile("cp.async.commit_group;\n");
}
__device__ __forceinline__ void cp_wait1() {
    asm volatile("cp.async.wait_group 1;\n");
}
__device__ __forceinline__ void cp_wait0() {
    asm volatile("cp.async.wait_group 0;\n");
}
// Legacy fp16 tensor-core MMA (sm_80+, valid on base sm_100):
// D[16x8](f32) += A[16x16](f16) * B[16x8](f16)
__device__ __forceinline__ void mma_f16(float& c0, float& c1, float& c2, float& c3,
                                        uint32_t a0, uint32_t a1, uint32_t a2, uint32_t a3,
                                        uint32_t b0, uint32_t b1) {
    asm volatile(
        "mma.sync.aligned.m16n8k16.row.col.f32.f16.f16.f32 "
        "{%0,%1,%2,%3}, {%4,%5,%6,%7}, {%8,%9}, {%0,%1,%2,%3};\n"
        : "+f"(c0), "+f"(c1), "+f"(c2), "+f"(c3)
        : "r"(a0), "r"(a1), "r"(a2), "r"(a3), "r"(b0), "r"(b1));
}

// ---------------------------------------------------------------------------
// Kernel: zero block masks
// ---------------------------------------------------------------------------
__global__ void zero_mask_kernel(int n) {
    int i = blockIdx.x * 256 + threadIdx.x;
    if (i < n) g_maskbits[i] = 0u;
}

// ---------------------------------------------------------------------------
// Kernel: gating (one warp per token) — proven Rounds 1-5
// ---------------------------------------------------------------------------
__global__ void gate_kernel(const float* __restrict__ x,
                            const float* __restrict__ gw,
                            const float* __restrict__ gb,
                            int B) {
    __shared__ float s_gw[N_EXP * D_MODEL];
    __shared__ float s_gb[N_EXP];
    int tid = threadIdx.x;
    for (int i = tid; i < N_EXP * D_MODEL; i += 256) s_gw[i] = gw[i];
    if (tid < N_EXP) s_gb[tid] = gb[tid];
    __syncthreads();

    int warp = tid >> 5, lane = tid & 31;
    int token = blockIdx.x * 8 + warp;
    if (token >= B) return;

    const float* xr = x + (size_t)token * D_MODEL;
    float xv[8];
#pragma unroll
    for (int i = 0; i < 8; i++) xv[i] = xr[lane + 32 * i];

    float logits[N_EXP];
#pragma unroll
    for (int e = 0; e < N_EXP; e++) {
        float p = 0.f;
#pragma unroll
        for (int i = 0; i < 8; i++) p += xv[i] * s_gw[e * D_MODEL + lane + 32 * i];
#pragma unroll
        for (int off = 16; off > 0; off >>= 1) p += __shfl_xor_sync(0xffffffffu, p, off);
        logits[e] = p + s_gb[e];
    }
    float mx = logits[0]; int amax = 0;
#pragma unroll
    for (int e = 1; e < N_EXP; e++) if (logits[e] > mx) { mx = logits[e]; amax = e; }
    float sum = 0.f;
#pragma unroll
    for (int e = 0; e < N_EXP; e++) { logits[e] = expf(logits[e] - mx); sum += logits[e]; }
    float inv = 1.f / sum;
    if (lane < N_EXP) g_coef[(size_t)token * N_EXP + lane] = logits[lane] * inv;
    if (lane == 0)    atomicOr(&g_maskbits[token >> 8], 1u << amax);
}

// ---------------------------------------------------------------------------
// Kernel: prep A  (x f32 -> fp16 rn, same [b][k] layout)
// ---------------------------------------------------------------------------
__global__ void prep_A_kernel(const float* __restrict__ x, int n4) {
    int i = blockIdx.x * 256 + threadIdx.x;
    if (i >= n4) return;
    float4 v = ((const float4*)x)[i];
    union { __half h[4]; uint2 u; } p;
    p.h[0] = __float2half_rn(v.x); p.h[1] = __float2half_rn(v.y);
    p.h[2] = __float2half_rn(v.z); p.h[3] = __float2half_rn(v.w);
    ((uint2*)g_Ah)[i] = p.u;
}

// ---------------------------------------------------------------------------
// Kernel: prep B  (w[k, e*256+n] f32 -> fp16, TRANSPOSED to g_Bh[e][n][k])
//   grid = 16 * 8 * 8 blocks (e, kblk, nblk), 256 threads, 32x32 tile
// ---------------------------------------------------------------------------
__global__ void prep_B_kernel(const float* __restrict__ w) {
    __shared__ float tile[32][33];
    int bid = blockIdx.x;
    int e = bid >> 6, kb = (bid >> 3) & 7, nb = bid & 7;
    int k0 = kb * 32, n0 = nb * 32;
    int t = threadIdx.x;
    {
        int ki = t >> 5, nj = t & 31;
#pragma unroll
        for (int it = 0; it < 4; it++)
            tile[ki + it * 8][nj] =
                w[(size_t)(k0 + ki + it * 8) * (N_EXP * D_MODEL) + e * D_MODEL + n0 + nj];
    }
    __syncthreads();
    {
        int n = t >> 3, part = t & 7;
        union { __half h[4]; uint2 u; } p;
#pragma unroll
        for (int j = 0; j < 4; j++) p.h[j] = __float2half_rn(tile[part * 4 + j][n]);
        *(uint2*)(g_Bh + (size_t)(e * D_MODEL + n0 + n) * D_MODEL + k0 + part * 4) = p.u;
    }
}

// ---------------------------------------------------------------------------
// Main kernel: legacy fp16 HMMA MoE GEMM (m16n8k16).
//   CTA = 128 tokens x 128 out-cols, 256 threads (8 warps, warp tile 64x32).
//   A tile (128x256 fp16) SMEM-resident, reused by all 16 experts.
//   B slab per (e, kc) = 128n x 32k fp16 [n][k], 3-buffer cp.async ring.
//   Per expert: cfrag += A@B_e; at expert end: out += coef[row,e]*cfrag.
// ---------------------------------------------------------------------------
#define AS32 132     // A row stride in b32 (264 halfs, 528B); 132%32==4 -> conflict-free
#define BS32 36      // B n-row stride in b32 (72 halfs, 144B); 36%32==4 -> conflict-free
#define CSTRIDE 17
#define SM_A   0                                   // 128 * 528  = 67584 B
#define SM_B   67584                               // 3 * 128*144 = 55296 B
#define SM_C   122880                              // 128*17*4    = 8704 B
#define SMEM_BYTES 131584

__global__ void __launch_bounds__(256, 1)
moe_mma_kernel(float* __restrict__ out, int B) {
    extern __shared__ char sm[];
    uint32_t* s_a32 = (uint32_t*)(sm + SM_A);
    float*    s_c   = (float*)(sm + SM_C);

    const int tid  = threadIdx.x;
    const int wid  = tid >> 5;
    const int lane = tid & 31;
    const int gid  = lane >> 2;          // 0..7
    const int tig  = lane & 3;           // 0..3
    const int warp_m = wid & 1;          // 64 rows each
    const int warp_n = wid >> 1;         // 32 cols each

    const int mblk  = blockIdx.x >> 1;
    const int nhalf = blockIdx.x & 1;
    const size_t t0 = (size_t)mblk * 128;

    // ---- coefficients (masked) into SMEM ----
    {
        unsigned mb = g_maskbits[(unsigned)(t0 >> 8)];
#pragma unroll
        for (int it = 0; it < 8; it++) {
            int idx = it * 256 + tid;
            int r = idx >> 4, e = idx & 15;
            float c = g_coef[(t0 + r) * N_EXP + e];
            s_c[r * CSTRIDE + e] = ((mb >> e) & 1u) ? c : 0.f;
        }
    }

    // ---- A tile: 128 rows x 512B via cp.async (32 chunks/row) ----
    {
        const char* asrc = (const char*)(g_Ah + t0 * D_MODEL);
#pragma unroll
        for (int it = 0; it < 16; it++) {
            int idx = it * 256 + tid;            // 4096 chunks
            int r = idx >> 5, c = idx & 31;
            cp_async16(sm + SM_A + r * 528 + c * 16, asrc + (size_t)r * 512 + c * 16);
        }
    }
    // ---- slab issue: i = (e = i>>3, kc = i&7): 128 n-rows x 32 k-halfs ----
    auto issue_slab = [&](int i) {
        int e = i >> 3, kc = i & 7;
        char* dst = sm + SM_B + (i % 3) * (128 * 144);
        const char* src = (const char*)(g_Bh
            + (size_t)(e * D_MODEL + nhalf * 128) * D_MODEL + kc * 32);
#pragma unroll
        for (int it = 0; it < 2; it++) {
            int idx = it * 256 + tid;            // 512 chunks
            int n = idx >> 2, c = idx & 3;
            cp_async16(dst + n * 144 + c * 16, src + (size_t)n * 512 + c * 16);
        }
        cp_commit();
    };
    issue_slab(0);   // group: {A + slab0}

    float o[4][4][4];
#pragma unroll
    for (int mt = 0; mt < 4; mt++)
#pragma unroll
        for (int nt = 0; nt < 4; nt++)
#pragma unroll
            for (int j = 0; j < 4; j++) o[mt][nt][j] = 0.f;

    float cf[4][4][4];

#pragma unroll 1
    for (int i = 0; i < 128; i++) {
        const int kc = i & 7;
        if (i + 1 < 128) { issue_slab(i + 1); cp_wait1(); }
        else             { cp_wait0(); }
        __syncthreads();

        if (kc == 0) {
#pragma unroll
            for (int mt = 0; mt < 4; mt++)
#pragma unroll
                for (int nt = 0; nt < 4; nt++)
#pragma unroll
                    for (int j = 0; j < 4; j++) cf[mt][nt][j] = 0.f;
        }

        const uint32_t* bb = (const uint32_t*)(sm + SM_B + (i % 3) * (128 * 144));

#pragma unroll
        for (int k16 = 0; k16 < 2; k16++) {
            const int kb = kc * 16 + k16 * 8;     // b32 offset into A row
            uint32_t a[4][4];
#pragma unroll
            for (int mt = 0; mt < 4; mt++) {
                int r0 = warp_m * 64 + mt * 16 + gid;
                int base = r0 * AS32 + kb + tig;
                a[mt][0] = s_a32[base];
                a[mt][1] = s_a32[base + 8 * AS32];
                a[mt][2] = s_a32[base + 4];
                a[mt][3] = s_a32[base + 4 + 8 * AS32];
            }
            uint32_t b[4][2];
#pragma unroll
            for (int nt = 0; nt < 4; nt++) {
                int col = warp_n * 32 + nt * 8 + gid;
                int bbase = col * BS32 + k16 * 8 + tig;
                b[nt][0] = bb[bbase];
                b[nt][1] = bb[bbase + 4];
            }
#pragma unroll
            for (int mt = 0; mt < 4; mt++)
#pragma unroll
                for (int nt = 0; nt < 4; nt++)
                    mma_f16(cf[mt][nt][0], cf[mt][nt][1], cf[mt][nt][2], cf[mt][nt][3],
                            a[mt][0], a[mt][1], a[mt][2], a[mt][3],
                            b[nt][0], b[nt][1]);
        }

        if (kc == 7) {
            const int e = i >> 3;
#pragma unroll
            for (int mt = 0; mt < 4; mt++) {
                int r0 = warp_m * 64 + mt * 16 + gid;
                float c0 = s_c[r0 * CSTRIDE + e];
                float c1 = s_c[(r0 + 8) * CSTRIDE + e];
#pragma unroll
                for (int nt = 0; nt < 4; nt++) {
                    o[mt][nt][0] = fmaf(c0, cf[mt][nt][0], o[mt][nt][0]);
                    o[mt][nt][1] = fmaf(c0, cf[mt][nt][1], o[mt][nt][1]);
                    o[mt][nt][2] = fmaf(c1, cf[mt][nt][2], o[mt][nt][2]);
                    o[mt][nt][3] = fmaf(c1, cf[mt][nt][3], o[mt][nt][3]);
                }
            }
        }
    }

    // ---- epilogue: float2 stores ----
#pragma unroll
    for (int mt = 0; mt < 4; mt++) {
        size_t r0 = t0 + warp_m * 64 + mt * 16 + gid;
#pragma unroll
        for (int nt = 0; nt < 4; nt++) {
            int col = nhalf * 128 + warp_n * 32 + nt * 8 + 2 * tig;
            *(float2*)(out + r0 * D_MODEL + col)       = make_float2(o[mt][nt][0], o[mt][nt][1]);
            *(float2*)(out + (r0 + 8) * D_MODEL + col) = make_float2(o[mt][nt][2], o[mt][nt][3]);
        }
    }
}

// ---------------------------------------------------------------------------
// Launch
// ---------------------------------------------------------------------------
extern "C" void kernel_launch(void* const* d_in, const int* in_sizes, int n_in,
                              void* d_out, int out_size) {
    const float* x  = (const float*)d_in[0];
    const float* w  = (const float*)d_in[1];
    const float* gw = (const float*)d_in[2];
    const float* gb = (const float*)d_in[3];
    float* out = (float*)d_out;

    int B = in_sizes[0] / D_MODEL;
    int nblk256 = B / 256;

    zero_mask_kernel<<<(nblk256 + 255) / 256, 256>>>(nblk256);
    gate_kernel<<<B / 8, 256>>>(x, gw, gb, B);

    int nA4 = (B * D_MODEL) / 4;
    prep_A_kernel<<<(nA4 + 255) / 256, 256>>>(x, nA4);
    prep_B_kernel<<<N_EXP * 8 * 8, 256>>>(w);

    cudaFuncSetAttribute(moe_mma_kernel,
                         cudaFuncAttributeMaxDynamicSharedMemorySize, SMEM_BYTES);
    moe_mma_kernel<<<(B / 128) * 2, 256, SMEM_BYTES>>>(out, B);
}